// round 8
// baseline (speedup 1.0000x reference)
#include <cuda_runtime.h>
#include <cstdint>

// B=4, P2=64, TOPK=16, W2=49, C_KV=512
// r_idx: int32 (B, P2, TOPK)    [JAX x64-off emits int32]
// kv:    float32 (B, P2, W2, C_KV)
// out:   float32 (B, P2, TOPK, W2, C_KV)
//
// TMA bulk multicast gather. Block = (chunk 0..3, src 0..255):
//   1. cp.async.bulk G->S: load this src's 25088B quarter-region into SMEM
//      (single thread issues; TMA engine does the work)
//   2. concurrently, 128 threads scan the batch's 1024 r_idx entries into a
//      shared dest list
//   3. one thread issues cnt cp.async.bulk S->G stores of the SAME smem chunk
//      to all destinations. SM-side store-issue cost -> ~zero; writes stream
//      from the TMA/LTS path with deep pipelining.

#define B_    4
#define P2_   64
#define TOPK_ 16
#define W2_   49
#define CKV_  512

#define RPB_          (P2_ * TOPK_)             // 1024 dest regions per batch
#define REGION_BYTES  (W2_ * CKV_ * 4)          // 100352
#define CHUNKS_       4
#define CHUNK_BYTES   (REGION_BYTES / CHUNKS_)  // 25088
#define THREADS_      128

__device__ __forceinline__ uint32_t smem_u32(const void* p) {
    return (uint32_t)__cvta_generic_to_shared(p);
}

__global__ void __launch_bounds__(THREADS_, 7) kv_gather_kernel(
    const int*  __restrict__ r_idx,
    const char* __restrict__ kv,
    char*       __restrict__ out)
{
    __shared__ alignas(128) char s_data[CHUNK_BYTES];
    __shared__ int s_list[RPB_];
    __shared__ int s_cnt;
    __shared__ alignas(8) unsigned long long s_mbar;

    const int t     = threadIdx.x;
    const int chunk = blockIdx.x;               // 0..3
    const int src   = blockIdx.y;               // 0..255 = b*64 + r
    const int b     = src >> 6;
    const int r     = src & 63;

    const uint32_t mbar = smem_u32(&s_mbar);
    const uint32_t sdat = smem_u32(s_data);

    if (t == 0) {
        s_cnt = 0;
        asm volatile("mbarrier.init.shared.b64 [%0], 1;" :: "r"(mbar) : "memory");
        // make mbarrier init visible to the async proxy before the bulk op
        asm volatile("fence.proxy.async.shared::cta;" ::: "memory");
        // kick off the bulk load of this source chunk
        asm volatile("mbarrier.arrive.expect_tx.shared.b64 _, [%0], %1;"
                     :: "r"(mbar), "r"((uint32_t)CHUNK_BYTES) : "memory");
        const char* gsrc = kv + (long long)src * REGION_BYTES
                              + (long long)chunk * CHUNK_BYTES;
        asm volatile(
            "cp.async.bulk.shared::cluster.global.mbarrier::complete_tx::bytes "
            "[%0], [%1], %2, [%3];"
            :: "r"(sdat), "l"(gsrc), "r"((uint32_t)CHUNK_BYTES), "r"(mbar)
            : "memory");
    }
    __syncthreads();   // also orders s_cnt=0 before the scan's atomics

    // Scan this batch's r_idx (1024 ints, L2-resident) while the TMA load runs.
    #pragma unroll
    for (int j = t; j < RPB_; j += THREADS_) {
        int ri = __ldg(&r_idx[b * RPB_ + j]);
        ri = min(max(ri, 0), P2_ - 1);
        if (ri == r) {
            int slot = atomicAdd(&s_cnt, 1);
            s_list[slot] = b * RPB_ + j;        // global dest region id
        }
    }
    __syncthreads();

    if (t == 0) {
        const int cnt = s_cnt;

        // wait for the bulk load (phase 0)
        {
            uint32_t done;
            asm volatile(
                "{\n\t.reg .pred p;\n\t"
                "mbarrier.try_wait.parity.shared.b64 p, [%1], 0;\n\t"
                "selp.b32 %0, 1, 0, p;\n\t}"
                : "=r"(done) : "r"(mbar) : "memory");
            while (!done) {
                asm volatile(
                    "{\n\t.reg .pred p;\n\t"
                    "mbarrier.try_wait.parity.shared.b64 p, [%1], 0;\n\t"
                    "selp.b32 %0, 1, 0, p;\n\t}"
                    : "=r"(done) : "r"(mbar) : "memory");
            }
        }

        const long long coff = (long long)chunk * CHUNK_BYTES;
        // multicast the SMEM chunk to every destination via bulk stores
        for (int i = 0; i < cnt; i++) {
            char* gdst = out + (long long)s_list[i] * REGION_BYTES + coff;
            asm volatile(
                "cp.async.bulk.global.shared::cta.bulk_group [%0], [%1], %2;"
                :: "l"(gdst), "r"(sdat), "r"((uint32_t)CHUNK_BYTES)
                : "memory");
        }
        asm volatile("cp.async.bulk.commit_group;" ::: "memory");
        // SMEM is freed at CTA exit; wait until the bulk stores have READ it
        asm volatile("cp.async.bulk.wait_group.read 0;" ::: "memory");
    }
}

extern "C" void kernel_launch(void* const* d_in, const int* in_sizes, int n_in,
                              void* d_out, int out_size)
{
    const int*  r_idx = (const int*)d_in[0];
    const char* kv    = (const char*)d_in[1];
    char*       out   = (char*)d_out;

    dim3 grid(CHUNKS_, B_ * P2_);               // (4, 256)
    kv_gather_kernel<<<grid, THREADS_>>>(r_idx, kv, out);
}

// round 9
// speedup vs baseline: 1.1044x; 1.1044x over previous
#include <cuda_runtime.h>
#include <cstdint>

// B=4, P2=64, TOPK=16, W2=49, C_KV=512
// r_idx: int32 (B, P2, TOPK)    [JAX x64-off emits int32]
// kv:    float32 (B, P2, W2, C_KV)
// out:   float32 (B, P2, TOPK, W2, C_KV)
//
// Fused inverted multicast gather, 4x-unrolled store loop.
//   block = (chunk 0..6, src 0..255): scan batch's 1024 r_idx entries into a
//   shared dest list; read the 896-f4 source chunk ONCE into registers; then
//   multicast it, 4 destinations per iteration (8 independent STG.128 per
//   thread per iteration) so store issue isn't gated by the LDS->addr chain.
// LTS traffic: ~26MB reads + 411MB writes (R3's direct gather does 822MB and
// is pinned at the LTS cap of ~13TB/s).

#define B_    4
#define P2_   64
#define TOPK_ 16
#define W2_   49
#define CKV_  512

#define RPB_        (P2_ * TOPK_)           // 1024 dest regions per batch
#define REGION_F4   ((W2_ * CKV_) / 4)      // 6272 float4 per region
#define THREADS_    448
#define CHUNKS_     7
#define CHUNK_F4    (REGION_F4 / CHUNKS_)   // 896 (2 float4 per thread)

__global__ void __launch_bounds__(THREADS_, 4) kv_gather_kernel(
    const int*    __restrict__ r_idx,
    const float4* __restrict__ kv,
    float4*       __restrict__ out)
{
    __shared__ int s_cnt;
    __shared__ int s_list[RPB_];

    const int src   = blockIdx.y;           // 0..255 = b*64 + r
    const int chunk = blockIdx.x;           // 0..6
    const int b = src >> 6;
    const int r = src & 63;
    const int t = threadIdx.x;

    if (t == 0) s_cnt = 0;
    __syncthreads();

    // Scan this batch's r_idx (1024 ints, L2-resident) for matches.
    #pragma unroll
    for (int j = t; j < RPB_; j += THREADS_) {
        int ri = __ldg(&r_idx[b * RPB_ + j]);
        ri = min(max(ri, 0), P2_ - 1);
        if (ri == r) {
            int slot = atomicAdd(&s_cnt, 1);
            s_list[slot] = b * RPB_ + j;    // global dest region id
        }
    }
    __syncthreads();

    const int cnt = s_cnt;
    if (cnt == 0) return;

    // Read the source chunk ONCE: 2 coalesced float4 per thread.
    const unsigned src_off = (unsigned)src * REGION_F4 + (unsigned)chunk * CHUNK_F4;
    const float4 v0 = __ldg(&kv[src_off + t]);
    const float4 v1 = __ldg(&kv[src_off + THREADS_ + t]);

    const unsigned cb = (unsigned)chunk * CHUNK_F4 + (unsigned)t;

    // Multicast: 4 destinations per iteration -> 8 independent STG.128.
    int i = 0;
    for (; i + 4 <= cnt; i += 4) {
        const unsigned d0 = (unsigned)s_list[i + 0] * REGION_F4 + cb;
        const unsigned d1 = (unsigned)s_list[i + 1] * REGION_F4 + cb;
        const unsigned d2 = (unsigned)s_list[i + 2] * REGION_F4 + cb;
        const unsigned d3 = (unsigned)s_list[i + 3] * REGION_F4 + cb;
        __stcs(&out[d0],            v0);
        __stcs(&out[d1],            v0);
        __stcs(&out[d2],            v0);
        __stcs(&out[d3],            v0);
        __stcs(&out[d0 + THREADS_], v1);
        __stcs(&out[d1 + THREADS_], v1);
        __stcs(&out[d2 + THREADS_], v1);
        __stcs(&out[d3 + THREADS_], v1);
    }
    for (; i < cnt; i++) {
        const unsigned d = (unsigned)s_list[i] * REGION_F4 + cb;
        __stcs(&out[d],            v0);
        __stcs(&out[d + THREADS_], v1);
    }
}

extern "C" void kernel_launch(void* const* d_in, const int* in_sizes, int n_in,
                              void* d_out, int out_size)
{
    const int*    r_idx = (const int*)d_in[0];
    const float4* kv    = (const float4*)d_in[1];
    float4*       out   = (float4*)d_out;

    dim3 grid(CHUNKS_, B_ * P2_);           // (7, 256)
    kv_gather_kernel<<<grid, THREADS_>>>(r_idx, kv, out);
}

// round 10
// speedup vs baseline: 1.1790x; 1.0675x over previous
#include <cuda_runtime.h>
#include <cstdint>

// B=4, P2=64, TOPK=16, W2=49, C_KV=512
// r_idx: int32 (B, P2, TOPK)    [JAX x64-off emits int32]
// kv:    float32 (B, P2, W2, C_KV)
// out:   float32 (B, P2, TOPK, W2, C_KV)
//
// All-TMA direct gather. Block = (chunk 0..3, region 0..4095), 32 threads:
//   lane0: LDG r_idx (L2 hit) -> cp.async.bulk G->S of the 25088B source
//   chunk (L2-resident) -> mbarrier wait -> ONE cp.async.bulk S->G to the
//   destination. No per-thread LDG/STG at all: the LSU/L1TEX pipe (73% busy
//   in the best STG kernel, co-saturated with DRAM) leaves the data path.
//   16384 uniform blocks, ~8 CTAs/SM => ~200KB of TMA writes in flight/SM.

#define B_    4
#define P2_   64
#define TOPK_ 16
#define W2_   49
#define CKV_  512

#define N_REGIONS     (B_ * P2_ * TOPK_)        // 4096
#define REGION_BYTES  (W2_ * CKV_ * 4)          // 100352
#define CHUNKS_       4
#define CHUNK_BYTES   (REGION_BYTES / CHUNKS_)  // 25088

__device__ __forceinline__ uint32_t smem_u32(const void* p) {
    return (uint32_t)__cvta_generic_to_shared(p);
}

__global__ void __launch_bounds__(32) kv_gather_kernel(
    const int*  __restrict__ r_idx,
    const char* __restrict__ kv,
    char*       __restrict__ out)
{
    __shared__ alignas(128) char s_data[CHUNK_BYTES];
    __shared__ alignas(8) unsigned long long s_mbar;

    if (threadIdx.x != 0) return;

    const int chunk  = blockIdx.x;              // 0..3
    const int region = blockIdx.y;              // 0..4095
    const int b = region >> 10;                 // region / (P2*TOPK)

    int r = __ldg(&r_idx[region]);
    r = min(max(r, 0), P2_ - 1);

    const uint32_t mbar = smem_u32(&s_mbar);
    const uint32_t sdat = smem_u32(s_data);
    const long long coff = (long long)chunk * CHUNK_BYTES;

    // -- bulk load: source chunk (L2-resident) -> SMEM --
    asm volatile("mbarrier.init.shared.b64 [%0], 1;" :: "r"(mbar) : "memory");
    asm volatile("fence.proxy.async.shared::cta;" ::: "memory");
    asm volatile("mbarrier.arrive.expect_tx.shared.b64 _, [%0], %1;"
                 :: "r"(mbar), "r"((uint32_t)CHUNK_BYTES) : "memory");
    const char* gsrc = kv + (long long)(b * P2_ + r) * REGION_BYTES + coff;
    asm volatile(
        "cp.async.bulk.shared::cluster.global.mbarrier::complete_tx::bytes "
        "[%0], [%1], %2, [%3];"
        :: "r"(sdat), "l"(gsrc), "r"((uint32_t)CHUNK_BYTES), "r"(mbar)
        : "memory");

    // wait (phase 0)
    {
        uint32_t done = 0;
        do {
            asm volatile(
                "{\n\t.reg .pred p;\n\t"
                "mbarrier.try_wait.parity.shared.b64 p, [%1], 0;\n\t"
                "selp.b32 %0, 1, 0, p;\n\t}"
                : "=r"(done) : "r"(mbar) : "memory");
        } while (!done);
    }

    // -- bulk store: SMEM -> destination --
    char* gdst = out + (long long)region * REGION_BYTES + coff;
    asm volatile(
        "cp.async.bulk.global.shared::cta.bulk_group [%0], [%1], %2;"
        :: "l"(gdst), "r"(sdat), "r"((uint32_t)CHUNK_BYTES)
        : "memory");
    asm volatile("cp.async.bulk.commit_group;" ::: "memory");
    // SMEM is reused/freed at block exit: wait until the store has READ it
    asm volatile("cp.async.bulk.wait_group.read 0;" ::: "memory");
}

extern "C" void kernel_launch(void* const* d_in, const int* in_sizes, int n_in,
                              void* d_out, int out_size)
{
    const int*  r_idx = (const int*)d_in[0];
    const char* kv    = (const char*)d_in[1];
    char*       out   = (char*)d_out;

    dim3 grid(CHUNKS_, N_REGIONS);              // (4, 4096)
    kv_gather_kernel<<<grid, 32>>>(r_idx, kv, out);
}